// round 12
// baseline (speedup 1.0000x reference)
#include <cuda_runtime.h>
#include <math.h>

#define Bn 16
#define Cn 3
#define Hn 512
#define Wn 512
#define HW (Hn * Wn)           // 262144
#define CHW (Cn * HW)          // 786432
#define NTOT (Bn * Cn * HW)    // 12582912

// ---- K1: pure streaming residual (measured 6.26 TB/s) ----
#define K1_THREADS 256
#define K1_PX_PER_BLOCK (K1_THREADS * 8)   // 2048
#define K1_BPB (HW / K1_PX_PER_BLOCK)      // 128
#define K1_NBLK (K1_BPB * Bn)              // 2048

// ---- K2: vectorized stencil over r_det ----
#define TW 64
#define TH 64
#define HTH (TH + 2)           // 66 halo rows
#define HTW 68                 // padded row; idx k = gcol (w0-1+k), valid k in [0,66)
#define HTW_VALID 66
#define VPR 18                 // 18 gmem float4 vectors per halo row (gcols w0-4..w0+67)
#define NITEMS (HTH * VPR)     // 1188
#define K2_THREADS 512
#define GX (Wn / TW)           // 8
#define GY (Hn / TH)           // 8
#define K2_BPB (GX * GY)       // 64
#define K2_NBLK (K2_BPB * Bn)  // 1024

__device__ float g_rdet[Bn * HW];    // signed residual (sign bit = mask)
__device__ float g_p1sum[K1_NBLK];
__device__ float g_p1sq[K1_NBLK];
__device__ float g_p2S[K2_NBLK];
__device__ unsigned int g_count;     // zero-init; last K2 block resets

__device__ __forceinline__ int reflect(int i, int n) {
    return (i < 0) ? -i : ((i >= n) ? 2 * n - 2 - i : i);
}
__device__ __forceinline__ float sgnsel(float rs, float re) {
    return (rs < re) ? __int_as_float(__float_as_int(rs) | 0x80000000u) : rs;
}

// ===========================================================================
// K1: streaming signed residual + per-block patch-sum partials (unchanged).
// ===========================================================================
__global__ __launch_bounds__(K1_THREADS) void residual_kernel(
    const float* __restrict__ sr,
    const float* __restrict__ srema,
    const float* __restrict__ hr)
{
    const int tid   = threadIdx.x;
    const int bid   = blockIdx.x;
    const int b     = bid >> 7;
    const int chunk = bid & 127;
    const int base  = b * CHW;
    const int p0    = chunk * K1_PX_PER_BLOCK;

    float lsum = 0.f, lsq = 0.f;
#pragma unroll
    for (int k = 0; k < 2; ++k) {
        const int p  = p0 + (tid + k * K1_THREADS) * 4;
        const int ix = base + p;

        float4 h0v = __ldg((const float4*)(hr    + ix));
        float4 s0v = __ldg((const float4*)(sr    + ix));
        float4 e0v = __ldg((const float4*)(srema + ix));
        float4 h1v = __ldg((const float4*)(hr    + ix + HW));
        float4 s1v = __ldg((const float4*)(sr    + ix + HW));
        float4 e1v = __ldg((const float4*)(srema + ix + HW));
        float4 h2v = __ldg((const float4*)(hr    + ix + 2 * HW));
        float4 s2v = __ldg((const float4*)(sr    + ix + 2 * HW));
        float4 e2v = __ldg((const float4*)(srema + ix + 2 * HW));

        float4 o4;
        {
            float rs = fabsf(h0v.x-s0v.x) + fabsf(h1v.x-s1v.x) + fabsf(h2v.x-s2v.x);
            float re = fabsf(h0v.x-e0v.x) + fabsf(h1v.x-e1v.x) + fabsf(h2v.x-e2v.x);
            o4.x = sgnsel(rs, re); lsum += rs; lsq += rs * rs;
        }
        {
            float rs = fabsf(h0v.y-s0v.y) + fabsf(h1v.y-s1v.y) + fabsf(h2v.y-s2v.y);
            float re = fabsf(h0v.y-e0v.y) + fabsf(h1v.y-e1v.y) + fabsf(h2v.y-e2v.y);
            o4.y = sgnsel(rs, re); lsum += rs; lsq += rs * rs;
        }
        {
            float rs = fabsf(h0v.z-s0v.z) + fabsf(h1v.z-s1v.z) + fabsf(h2v.z-s2v.z);
            float re = fabsf(h0v.z-e0v.z) + fabsf(h1v.z-e1v.z) + fabsf(h2v.z-e2v.z);
            o4.z = sgnsel(rs, re); lsum += rs; lsq += rs * rs;
        }
        {
            float rs = fabsf(h0v.w-s0v.w) + fabsf(h1v.w-s1v.w) + fabsf(h2v.w-s2v.w);
            float re = fabsf(h0v.w-e0v.w) + fabsf(h1v.w-e1v.w) + fabsf(h2v.w-e2v.w);
            o4.w = sgnsel(rs, re); lsum += rs; lsq += rs * rs;
        }
        *(float4*)(g_rdet + b * HW + p) = o4;
    }

    __shared__ float wsum[8], wsq[8];
#pragma unroll
    for (int o = 16; o > 0; o >>= 1) {
        lsum += __shfl_down_sync(0xffffffffu, lsum, o);
        lsq  += __shfl_down_sync(0xffffffffu, lsq,  o);
    }
    const int warp = tid >> 5;
    if ((tid & 31) == 0) { wsum[warp] = lsum; wsq[warp] = lsq; }
    __syncthreads();
    if (tid == 0) {
        float a = 0.f, c = 0.f;
#pragma unroll
        for (int i = 0; i < 8; ++i) { a += wsum[i]; c += wsq[i]; }
        g_p1sum[bid] = a;
        g_p1sq[bid]  = c;
    }
}

// Write 4 residuals to smem row idx [4v-3 .. 4v], clipped to [0, HTW_VALID)
__device__ __forceinline__ void store4(float* __restrict__ row, int v,
                                       float x, float y, float z, float w) {
    const int i0 = 4 * v - 3;
    if (i0     >= 0 && i0     < HTW_VALID) row[i0]     = x;
    if (i0 + 1 >= 0 && i0 + 1 < HTW_VALID) row[i0 + 1] = y;
    if (i0 + 2 >= 0 && i0 + 2 < HTW_VALID) row[i0 + 2] = z;
    if (i0 + 3 < HTW_VALID)                row[i0 + 3] = w;
}

// 6 window values -> 4 overlapping 3-sums (abs and square)
__device__ __forceinline__ void rowsums(float4 a, float4 b2, float* A, float* B) {
    float p0 = fabsf(a.x), p1 = fabsf(a.y), p2 = fabsf(a.z);
    float p3 = fabsf(a.w), p4 = fabsf(b2.x), p5 = fabsf(b2.y);
    float q0 = p0 * p0, q1 = p1 * p1, q2 = p2 * p2;
    float q3 = p3 * p3, q4 = p4 * p4, q5 = p5 * p5;
    A[0] = p0 + p1 + p2;  A[1] = p1 + p2 + p3;
    A[2] = p2 + p3 + p4;  A[3] = p3 + p4 + p5;
    B[0] = q0 + q1 + q2;  B[1] = q1 + q2 + q3;
    B[2] = q2 + q3 + q4;  B[3] = q3 + q4 + q5;
}

// ===========================================================================
// K2: 3x3 unbiased local variance over |r_det| (vectorized), last-block finalize.
// ===========================================================================
__global__ __launch_bounds__(K2_THREADS) void loss_kernel(float* __restrict__ out)
{
    __shared__ float rt[HTH * HTW];   // idx k = gcol w0-1+k (owned col c -> idx c+1)

    const int tid = threadIdx.x;
    const int w0  = blockIdx.x * TW;
    const int h0  = blockIdx.y * TH;
    const int b   = blockIdx.z;
    const float* __restrict__ rd = g_rdet + b * HW;

    // --- tile build (1188 items, 512 threads: 2 passes + 164 tail) ----------
    const bool interior = (blockIdx.x > 0 && blockIdx.x < GX - 1);
#pragma unroll
    for (int k = 0; k < 3; ++k) {
        const int t = tid + k * K2_THREADS;
        if (k == 2 && t >= NITEMS) break;
        const int ty  = t / VPR;
        const int v   = t - ty * VPR;
        const int gh  = reflect(h0 - 1 + ty, Hn);
        const int gw0 = w0 - 4 + 4 * v;
        float4 o4;
        if (interior || (gw0 >= 0 && gw0 + 3 < Wn)) {
            o4 = __ldg((const float4*)(rd + gh * Wn + gw0));
        } else {
            o4.x = __ldg(rd + gh * Wn + reflect(gw0,     Wn));
            o4.y = __ldg(rd + gh * Wn + reflect(gw0 + 1, Wn));
            o4.z = __ldg(rd + gh * Wn + reflect(gw0 + 2, Wn));
            o4.w = __ldg(rd + gh * Wn + reflect(gw0 + 3, Wn));
        }
        store4(rt + ty * HTW, v, o4.x, o4.y, o4.z, o4.w);
    }
    __syncthreads();

    // --- stencil: 4-pixel groups, 6 LDS.128 each ------------------------------
    // Group g: owned row r = g>>4, cols c0..c0+3 (c0 = (g&15)*4).
    // Window = rows r..r+2 (halo), cols idx c0..c0+5 -> float4s at c0, c0+4.
    float lS = 0.f;
#pragma unroll
    for (int k = 0; k < 2; ++k) {
        const int g  = tid + k * K2_THREADS;
        const int r  = g >> 4;
        const int c0 = (g & 15) << 2;
        const float* bp = rt + r * HTW + c0;

        float4 t0a = *(const float4*)(bp);
        float4 t0b = *(const float4*)(bp + 4);
        float4 t1a = *(const float4*)(bp + HTW);
        float4 t1b = *(const float4*)(bp + HTW + 4);
        float4 t2a = *(const float4*)(bp + 2 * HTW);
        float4 t2b = *(const float4*)(bp + 2 * HTW + 4);

        float A0[4], B0[4], A1[4], B1[4], A2[4], B2[4];
        rowsums(t0a, t0b, A0, B0);
        rowsums(t1a, t1b, A1, B1);
        rowsums(t2a, t2b, A2, B2);

        const float cen[4] = { t1a.y, t1a.z, t1a.w, t1b.x };
#pragma unroll
        for (int x = 0; x < 4; ++x) {
            float s  = A0[x] + A1[x] + A2[x];
            float sq = B0[x] + B1[x] + B2[x];
            float lv = (sq - s * s * (1.0f / 9.0f)) * (1.0f / 8.0f);
            float r4 = fabsf(cen[x]);
            lS += signbit(cen[x]) ? 0.0f : fabsf(lv) * r4;
        }
    }

    __shared__ float wS[16];
#pragma unroll
    for (int o = 16; o > 0; o >>= 1)
        lS += __shfl_down_sync(0xffffffffu, lS, o);
    const int warp = tid >> 5;
    const int lane = tid & 31;
    if (lane == 0) wS[warp] = lS;
    __syncthreads();

    __shared__ bool isLast;
    if (tid == 0) {
        float d = 0.f;
#pragma unroll
        for (int i = 0; i < 16; ++i) d += wS[i];
        const int bid2 = blockIdx.x + GX * blockIdx.y + K2_BPB * blockIdx.z;
        g_p2S[bid2] = d;
        __threadfence();
        unsigned prev = atomicAdd(&g_count, 1u);
        isLast = (prev == K2_NBLK - 1);
    }
    __syncthreads();

    // --- finalize: patch weights + loss (16 warps, one per batch) ------------
    if (isLast) {
        if (tid == 0) g_count = 0;   // reset for graph replay
        __shared__ float sres[Bn];
        const int bb = warp;         // warp per batch
        float s = 0.f, sq = 0.f, S = 0.f;
#pragma unroll
        for (int e = 0; e < 4; ++e) {     // K1: 128 partials per batch
            const int i1 = bb * K1_BPB + lane * 4 + e;
            s  += __ldcg(&g_p1sum[i1]);
            sq += __ldcg(&g_p1sq[i1]);
        }
#pragma unroll
        for (int e = 0; e < 2; ++e) {     // K2: 64 partials per batch
            const int i2 = bb * K2_BPB + lane * 2 + e;
            S += __ldcg(&g_p2S[i2]);
        }
#pragma unroll
        for (int o = 16; o > 0; o >>= 1) {
            s  += __shfl_down_sync(0xffffffffu, s,  o);
            sq += __shfl_down_sync(0xffffffffu, sq, o);
            S  += __shfl_down_sync(0xffffffffu, S,  o);
        }
        if (lane == 0) {
            const float n = (float)HW;
            float var = (sq - s * s / n) / (n - 1.0f);   // raw scale
            float w = (var > 0.0f) ? exp2f(0.2f * log2f(var)) : 0.0f;
            sres[bb] = w * S;
        }
        __syncthreads();
        if (tid == 0) {
            float acc = 0.f;
#pragma unroll
            for (int i = 0; i < Bn; ++i) acc += sres[i];
            // loss = 255^(-2.4)/NTOT * sum_b var_raw^0.2 * S_raw
            double Kd = pow(255.0, -2.4) / (double)NTOT;
            out[0] = (float)((double)acc * Kd);
        }
    }
}

// ---------------------------------------------------------------------------
extern "C" void kernel_launch(void* const* d_in, const int* in_sizes, int n_in,
                              void* d_out, int out_size) {
    const float* sr    = (const float*)d_in[0];
    const float* srema = (const float*)d_in[1];
    const float* hr    = (const float*)d_in[2];
    float* out = (float*)d_out;

    residual_kernel<<<K1_NBLK, K1_THREADS>>>(sr, srema, hr);
    dim3 blk(K2_THREADS, 1, 1);
    dim3 grd(GX, GY, Bn);
    loss_kernel<<<grd, blk>>>(out);
}